// round 3
// baseline (speedup 1.0000x reference)
#include <cuda_runtime.h>
#include <cstdint>

// Problem constants
#define B_   2048
#define MND  128
#define D_   512
#define H_   512
#define KB   2048   // big-GEMM K = 4*512

// Scratch (device globals: no allocations allowed)
__device__ float g_X[(size_t)B_ * KB];      // [2048,2048] = [img_mean|txt_mean|it|ii] (tf32-rounded)
__device__ float g_Wbig[(size_t)H_ * KB];   // [512,2048]  = [W_l_img|W_l_txt|Wc]     (tf32-rounded)
__device__ float g_Wrc[H_ * H_];            // W_r_img + W_r_txt (fp32)
__device__ float g_bc[H_];                  // combined bias (fp32)

// Round fp32 -> tf32 (rna)
__device__ __forceinline__ float tf32r(float x) {
    uint32_t u;
    asm("cvt.rna.tf32.f32 %0, %1;" : "=r"(u) : "f"(x));
    return __uint_as_float(u);
}

// ---------------------------------------------------------------------------
// prep: Wbig[:,0:512]=W_l_img, Wbig[:,512:1024]=W_l_txt (tf32), Wrc = Wr_img+Wr_txt
// ---------------------------------------------------------------------------
__global__ void prep_kernel(const float* __restrict__ Wl_img,
                            const float* __restrict__ Wl_txt,
                            const float* __restrict__ Wr_img,
                            const float* __restrict__ Wr_txt) {
    int idx = blockIdx.x * blockDim.x + threadIdx.x;      // 0 .. 524287
    if (idx < H_ * 1024) {
        int h = idx >> 10, c = idx & 1023;
        float v = (c < 512) ? Wl_img[h * 512 + c] : Wl_txt[h * 512 + (c - 512)];
        g_Wbig[h * KB + c] = tf32r(v);
    }
    if (idx < H_ * H_) g_Wrc[idx] = Wr_img[idx] + Wr_txt[idx];
}

// ---------------------------------------------------------------------------
// bc[h] = b_l_img[h] + b_l_txt[h] + sum_k Wrc[h,k] * b_user[k]   (exact fp32)
// ---------------------------------------------------------------------------
__global__ void bc_kernel(const float* __restrict__ b_user,
                          const float* __restrict__ bl_img,
                          const float* __restrict__ bl_txt) {
    int h = blockIdx.x;
    int t = threadIdx.x;  // 128 threads
    float s = 0.0f;
    for (int k = t; k < H_; k += 128) s += g_Wrc[h * H_ + k] * b_user[k];
    __shared__ float red[4];
    #pragma unroll
    for (int o = 16; o; o >>= 1) s += __shfl_down_sync(0xffffffffu, s, o);
    if ((t & 31) == 0) red[t >> 5] = s;
    __syncthreads();
    if (t == 0)
        g_bc[h] = red[0] + red[1] + red[2] + red[3] + bl_img[h] + bl_txt[h];
}

// ---------------------------------------------------------------------------
// means: X[b] = [mean_m img | mean_m txt | it | ii]  (tf32-rounded on write)
// HBM-bound stage (86% of peak): leave alone.
// ---------------------------------------------------------------------------
__global__ void means_kernel(const float* __restrict__ img,
                             const float* __restrict__ txt,
                             const float* __restrict__ it,
                             const float* __restrict__ ii) {
    int b = blockIdx.x;
    int t = threadIdx.x;             // 0..255
    int h4 = t & 127;                // float4 index within 512 floats
    const float* src = (t < 128) ? img : txt;
    const float4* base = (const float4*)(src + (size_t)b * MND * H_) + h4;

    float4 acc = make_float4(0.f, 0.f, 0.f, 0.f);
    #pragma unroll 16
    for (int m = 0; m < MND; m++) {
        float4 v = base[(size_t)m * (H_ / 4)];
        acc.x += v.x; acc.y += v.y; acc.z += v.z; acc.w += v.w;
    }
    const float inv = 1.0f / (float)MND;
    float4 o;
    o.x = tf32r(acc.x * inv); o.y = tf32r(acc.y * inv);
    o.z = tf32r(acc.z * inv); o.w = tf32r(acc.w * inv);

    float4* xrow = (float4*)(g_X + (size_t)b * KB);
    xrow[(t < 128 ? 0 : 128) + h4] = o;

    const float4* cs = (const float4*)(((t < 128) ? it : ii) + (size_t)b * D_);
    float4 c = cs[h4];
    c.x = tf32r(c.x); c.y = tf32r(c.y); c.z = tf32r(c.z); c.w = tf32r(c.w);
    xrow[(t < 128 ? 256 : 384) + h4] = c;
}

// ---------------------------------------------------------------------------
// Wc = Wrc @ W_user  (M=512, N=1024, K=512), exact fp32 SIMT. Hidden under means.
// ---------------------------------------------------------------------------
__global__ void gemm_nn_wc(const float* __restrict__ Wuser) {
    __shared__ float As[16][68];
    __shared__ float Bs[16][68];
    const int bn = blockIdx.x;
    const int bm = blockIdx.y;
    const int tid = threadIdx.x;
    const int tn = tid & 15, tm = tid >> 4;
    const int ar = tid >> 2, akv = tid & 3;
    const int brow = tid >> 4, bc4 = tid & 15;

    const float* Ap = g_Wrc + (size_t)(bm * 64 + ar) * 512 + akv * 4;
    const float* Bp = Wuser + (size_t)brow * 1024 + bn * 64 + bc4 * 4;

    float acc[4][4] = {};
    for (int k0 = 0; k0 < 512; k0 += 16) {
        float4 av = *(const float4*)(Ap + k0);
        float4 bv = *(const float4*)(Bp + (size_t)k0 * 1024);
        __syncthreads();
        As[akv * 4 + 0][ar] = av.x; As[akv * 4 + 1][ar] = av.y;
        As[akv * 4 + 2][ar] = av.z; As[akv * 4 + 3][ar] = av.w;
        *(float4*)&Bs[brow][bc4 * 4] = bv;
        __syncthreads();
        #pragma unroll
        for (int k = 0; k < 16; k++) {
            float4 a = *(const float4*)&As[k][tm * 4];
            float4 b = *(const float4*)&Bs[k][tn * 4];
            acc[0][0] += a.x * b.x; acc[0][1] += a.x * b.y; acc[0][2] += a.x * b.z; acc[0][3] += a.x * b.w;
            acc[1][0] += a.y * b.x; acc[1][1] += a.y * b.y; acc[1][2] += a.y * b.z; acc[1][3] += a.y * b.w;
            acc[2][0] += a.z * b.x; acc[2][1] += a.z * b.y; acc[2][2] += a.z * b.z; acc[2][3] += a.z * b.w;
            acc[3][0] += a.w * b.x; acc[3][1] += a.w * b.y; acc[3][2] += a.w * b.z; acc[3][3] += a.w * b.w;
        }
    }
    int row = bm * 64 + tm * 4;
    int col = bn * 64 + tn * 4;
    #pragma unroll
    for (int i = 0; i < 4; i++) {
        float4 v = make_float4(tf32r(acc[i][0]), tf32r(acc[i][1]),
                               tf32r(acc[i][2]), tf32r(acc[i][3]));
        *(float4*)&g_Wbig[(size_t)(row + i) * KB + 1024 + col] = v;
    }
}

// ---------------------------------------------------------------------------
// out = relu( X @ Wbig^T + bc )  via mma.sync.m16n8k8.tf32, cp.async 3-stage.
// BM=128, BN=64, BK=32, 256 threads (8 warps = 4m x 2n, warp tile 32x32).
// Smem stride 36 floats: frag LDS (4g+tg) mod 32 all distinct -> conflict-free.
// ---------------------------------------------------------------------------
#define GBM 128
#define GBN 64
#define GBK 32
#define ASTR 36
#define NST 3
#define SMEM_A_ELEMS (GBM * ASTR)          // 4608
#define SMEM_B_ELEMS (GBN * ASTR)          // 2304
#define GEMM_SMEM_BYTES (NST * (SMEM_A_ELEMS + SMEM_B_ELEMS) * 4)  // 82944

__device__ __forceinline__ void cp16(uint32_t saddr, const float* gaddr) {
    asm volatile("cp.async.cg.shared.global [%0], [%1], 16;\n"
                 :: "r"(saddr), "l"(gaddr));
}

__global__ __launch_bounds__(256) void gemm_out_tc(float* __restrict__ C) {
    extern __shared__ float sm[];
    float* As = sm;                             // [NST][GBM*ASTR]
    float* Bs = sm + NST * SMEM_A_ELEMS;        // [NST][GBN*ASTR]

    const int tid  = threadIdx.x;
    const int bn0  = blockIdx.x * GBN;
    const int bm0  = blockIdx.y * GBM;
    const int w    = tid >> 5;
    const int lane = tid & 31;
    const int wm   = (w & 3) * 32;
    const int wn   = (w >> 2) * 32;
    const int g    = lane >> 2;
    const int tg   = lane & 3;

    // load mapping: rows lr, lr+32, (A also +64,+96); k-chunk lc
    const int lr = tid >> 3;            // 0..31
    const int lc = (tid & 7) * 4;       // 0,4,..,28

    const float* Xg = g_X    + (size_t)(bm0 + lr) * KB + lc;
    const float* Wg = g_Wbig + (size_t)(bn0 + lr) * KB + lc;

    const uint32_t sA = (uint32_t)__cvta_generic_to_shared(As);
    const uint32_t sB = (uint32_t)__cvta_generic_to_shared(Bs);

    float acc[2][4][4];
    #pragma unroll
    for (int i = 0; i < 2; i++)
        #pragma unroll
        for (int j = 0; j < 4; j++)
            #pragma unroll
            for (int q = 0; q < 4; q++) acc[i][j][q] = 0.f;

    const int NKT = KB / GBK;   // 64

    // issue loads for stage s covering ktile kt
    auto issue = [&](int s, int kt) {
        const int kb = kt * GBK;
        uint32_t a0 = sA + (uint32_t)(s * SMEM_A_ELEMS + lr * ASTR + lc) * 4u;
        #pragma unroll
        for (int i = 0; i < 4; i++)
            cp16(a0 + (uint32_t)(i * 32 * ASTR) * 4u, Xg + kb + (size_t)(i * 32) * KB);
        uint32_t b0 = sB + (uint32_t)(s * SMEM_B_ELEMS + lr * ASTR + lc) * 4u;
        #pragma unroll
        for (int i = 0; i < 2; i++)
            cp16(b0 + (uint32_t)(i * 32 * ASTR) * 4u, Wg + kb + (size_t)(i * 32) * KB);
    };

    #pragma unroll
    for (int s = 0; s < NST; s++) {
        issue(s, s);
        asm volatile("cp.async.commit_group;\n" ::: "memory");
    }

    for (int kt = 0; kt < NKT; kt++) {
        const int p = kt % NST;
        asm volatile("cp.async.wait_group 2;\n" ::: "memory");
        __syncthreads();

        const float* Ap = As + p * SMEM_A_ELEMS;
        const float* Bp = Bs + p * SMEM_B_ELEMS;

        #pragma unroll
        for (int ks = 0; ks < 4; ks++) {
            const int k = ks * 8;
            uint32_t af[2][4], bf[4][2];
            #pragma unroll
            for (int mi = 0; mi < 2; mi++) {
                const int m = wm + mi * 16;
                af[mi][0] = __float_as_uint(Ap[(m + g)     * ASTR + k + tg]);
                af[mi][1] = __float_as_uint(Ap[(m + g + 8) * ASTR + k + tg]);
                af[mi][2] = __float_as_uint(Ap[(m + g)     * ASTR + k + tg + 4]);
                af[mi][3] = __float_as_uint(Ap[(m + g + 8) * ASTR + k + tg + 4]);
            }
            #pragma unroll
            for (int ni = 0; ni < 4; ni++) {
                const int n = wn + ni * 8;
                bf[ni][0] = __float_as_uint(Bp[(n + g) * ASTR + k + tg]);
                bf[ni][1] = __float_as_uint(Bp[(n + g) * ASTR + k + tg + 4]);
            }
            #pragma unroll
            for (int mi = 0; mi < 2; mi++)
                #pragma unroll
                for (int ni = 0; ni < 4; ni++)
                    asm volatile(
                        "mma.sync.aligned.m16n8k8.row.col.f32.tf32.tf32.f32 "
                        "{%0,%1,%2,%3}, {%4,%5,%6,%7}, {%8,%9}, {%0,%1,%2,%3};\n"
                        : "+f"(acc[mi][ni][0]), "+f"(acc[mi][ni][1]),
                          "+f"(acc[mi][ni][2]), "+f"(acc[mi][ni][3])
                        : "r"(af[mi][0]), "r"(af[mi][1]), "r"(af[mi][2]), "r"(af[mi][3]),
                          "r"(bf[ni][0]), "r"(bf[ni][1]));
        }

        __syncthreads();
        if (kt + NST < NKT) issue(p, kt + NST);
        asm volatile("cp.async.commit_group;\n" ::: "memory");
    }

    // epilogue: bias + ReLU
    #pragma unroll
    for (int mi = 0; mi < 2; mi++) {
        const int row0 = bm0 + wm + mi * 16 + g;
        #pragma unroll
        for (int ni = 0; ni < 4; ni++) {
            const int col = bn0 + wn + ni * 8 + tg * 2;
            const float b0v = g_bc[col], b1v = g_bc[col + 1];
            float2 v0, v1;
            v0.x = fmaxf(acc[mi][ni][0] + b0v, 0.f);
            v0.y = fmaxf(acc[mi][ni][1] + b1v, 0.f);
            v1.x = fmaxf(acc[mi][ni][2] + b0v, 0.f);
            v1.y = fmaxf(acc[mi][ni][3] + b1v, 0.f);
            *(float2*)&C[(size_t)row0 * H_ + col]       = v0;
            *(float2*)&C[(size_t)(row0 + 8) * H_ + col] = v1;
        }
    }
}

// ---------------------------------------------------------------------------
extern "C" void kernel_launch(void* const* d_in, const int* in_sizes, int n_in,
                              void* d_out, int out_size) {
    const float* it      = (const float*)d_in[0];
    const float* ii      = (const float*)d_in[1];
    const float* txt     = (const float*)d_in[2];
    const float* img     = (const float*)d_in[3];
    const float* W_user  = (const float*)d_in[4];
    const float* b_user  = (const float*)d_in[5];
    const float* Wl_img  = (const float*)d_in[6];
    const float* bl_img  = (const float*)d_in[7];
    const float* Wr_img  = (const float*)d_in[8];
    const float* Wl_txt  = (const float*)d_in[9];
    const float* bl_txt  = (const float*)d_in[10];
    const float* Wr_txt  = (const float*)d_in[11];
    float* out = (float*)d_out;

    cudaFuncSetAttribute(gemm_out_tc,
                         cudaFuncAttributeMaxDynamicSharedMemorySize,
                         GEMM_SMEM_BYTES);

    // Fork a side stream so the weight-prep chain overlaps the HBM-bound means.
    // (Event fork/join is graph-capturable; no syncs, no device allocations.)
    cudaStream_t s2;
    cudaEvent_t eFork, eJoin;
    cudaStreamCreateWithFlags(&s2, cudaStreamNonBlocking);
    cudaEventCreateWithFlags(&eFork, cudaEventDisableTiming);
    cudaEventCreateWithFlags(&eJoin, cudaEventDisableTiming);

    cudaEventRecord(eFork, 0);
    cudaStreamWaitEvent(s2, eFork, 0);

    // side stream: weight prep chain
    prep_kernel<<<2048, 256, 0, s2>>>(Wl_img, Wl_txt, Wr_img, Wr_txt);
    {
        dim3 grid(1024 / 64, 512 / 64);
        gemm_nn_wc<<<grid, 256, 0, s2>>>(W_user);
    }
    bc_kernel<<<512, 128, 0, s2>>>(b_user, bl_img, bl_txt);
    cudaEventRecord(eJoin, s2);

    // main stream: HBM-bound means (overlaps the above)
    means_kernel<<<B_, 256>>>(img, txt, it, ii);

    cudaStreamWaitEvent(0, eJoin, 0);

    // big GEMM: out = relu(X @ Wbig^T + bc)
    {
        dim3 grid(H_ / GBN, B_ / GBM);
        gemm_out_tc<<<grid, 256, GEMM_SMEM_BYTES>>>(out);
    }
}